// round 1
// baseline (speedup 1.0000x reference)
#include <cuda_runtime.h>
#include <math.h>

// Problem constants
#define B_SZ   2
#define L_SZ   1024
#define DM     256
#define H_SZ   8
#define DK     32
#define NROWS  (B_SZ * L_SZ)            // 2048
#define INV_SQRT_DK 0.17677669529663687f

#define TI 16          // i-rows per CTA in scores/emb kernels
#define TJ 32          // j-tile width
#define BS_PAD 36      // bias smem row pad (float4-aligned, conflict-free)
#define VS_PAD 33      // v smem row pad (odd -> conflict-free scalar reads)

// -------- scratch (no allocation allowed; __device__ globals) --------
__device__ float g_hn [NROWS * DM];
__device__ float g_q  [NROWS * DM];
__device__ float g_k  [NROWS * DM];
__device__ float g_v  [NROWS * DM];
__device__ float g_emb[NROWS * DM];

// ---------------------------------------------------------------
// LayerNorm: one CTA per (b,l) row of 256
// ---------------------------------------------------------------
__global__ void ln_kernel(const float* __restrict__ hin,
                          const float* __restrict__ gam,
                          const float* __restrict__ bta)
{
    int row = blockIdx.x, tid = threadIdx.x;
    float x = hin[(size_t)row * DM + tid];
    float s1 = x, s2 = x * x;
    #pragma unroll
    for (int o = 16; o; o >>= 1) {
        s1 += __shfl_xor_sync(0xffffffffu, s1, o);
        s2 += __shfl_xor_sync(0xffffffffu, s2, o);
    }
    __shared__ float r1[8], r2[8];
    __shared__ float mu_s, rstd_s;
    if ((tid & 31) == 0) { r1[tid >> 5] = s1; r2[tid >> 5] = s2; }
    __syncthreads();
    if (tid == 0) {
        float a = 0.f, c = 0.f;
        #pragma unroll
        for (int i = 0; i < 8; i++) { a += r1[i]; c += r2[i]; }
        float mu  = a * (1.0f / DM);
        float var = c * (1.0f / DM) - mu * mu;
        mu_s = mu; rstd_s = rsqrtf(var + 1e-5f);
    }
    __syncthreads();
    g_hn[(size_t)row * DM + tid] = (x - mu_s) * rstd_s * gam[tid] + bta[tid];
}

// ---------------------------------------------------------------
// Tiled GEMM:  C[M,N] = A[M,K] @ B[N,K]^T (+ bias[n]) (+ res[m,n])
// 64x64 tile, BK=16, 256 threads, 4x4 per thread
// ---------------------------------------------------------------
__global__ void gemm_abt_kernel(const float* __restrict__ A,
                                const float* __restrict__ Bm,
                                const float* __restrict__ bias,
                                const float* __restrict__ res,
                                float* __restrict__ C,
                                int M, int N, int K)
{
    __shared__ float As[16][64];
    __shared__ float Bs[16][64];
    int tid = threadIdx.x;
    int tx = tid & 15, ty = tid >> 4;
    int m0 = blockIdx.y * 64, n0 = blockIdx.x * 64;
    int lr = tid >> 2, lc = (tid & 3) * 4;
    float acc[4][4];
    #pragma unroll
    for (int i = 0; i < 4; i++)
        #pragma unroll
        for (int j = 0; j < 4; j++) acc[i][j] = 0.f;

    for (int k0 = 0; k0 < K; k0 += 16) {
        float4 av = *(const float4*)(A  + (size_t)(m0 + lr) * K + k0 + lc);
        float4 bv = *(const float4*)(Bm + (size_t)(n0 + lr) * K + k0 + lc);
        As[lc + 0][lr] = av.x; As[lc + 1][lr] = av.y; As[lc + 2][lr] = av.z; As[lc + 3][lr] = av.w;
        Bs[lc + 0][lr] = bv.x; Bs[lc + 1][lr] = bv.y; Bs[lc + 2][lr] = bv.z; Bs[lc + 3][lr] = bv.w;
        __syncthreads();
        #pragma unroll
        for (int kk = 0; kk < 16; kk++) {
            float a[4], bb[4];
            #pragma unroll
            for (int i = 0; i < 4; i++) a[i]  = As[kk][ty * 4 + i];
            #pragma unroll
            for (int j = 0; j < 4; j++) bb[j] = Bs[kk][tx * 4 + j];
            #pragma unroll
            for (int i = 0; i < 4; i++)
                #pragma unroll
                for (int j = 0; j < 4; j++)
                    acc[i][j] = fmaf(a[i], bb[j], acc[i][j]);
        }
        __syncthreads();
    }
    #pragma unroll
    for (int i = 0; i < 4; i++) {
        int m = m0 + ty * 4 + i;
        #pragma unroll
        for (int j = 0; j < 4; j++) {
            int n = n0 + tx * 4 + j;
            float v = acc[i][j];
            if (bias) v += bias[n];
            if (res)  v += res[(size_t)m * N + n];
            C[(size_t)m * N + n] = v;
        }
    }
}

// ---------------------------------------------------------------
// Scores: s[h,b,i,j] = (q_i,h . k_j,h + q_i,h . bias_i,j) / sqrt(32)
// Grid (2, NROWS/TI): x = j-half (512 each), y = 16-row block.
// Each warp owns one head h; lane = tj within 32-wide j tile.
// Writes RAW scores into the attn output region (normalized later).
// ---------------------------------------------------------------
__global__ void scores_kernel(const float* __restrict__ bias,
                              float* __restrict__ attn)
{
    extern __shared__ float sm[];
    float* qs = sm;             // TI*DM = 4096 floats
    float* bs = sm + TI * DM;   // TI*TJ*BS_PAD = 18432 floats

    int tid = threadIdx.x;
    int rb  = blockIdx.y;
    int jh  = blockIdx.x;
    int r0  = rb * TI;
    int b   = r0 >> 10;
    int i0  = r0 & (L_SZ - 1);

    {   // q rows -> smem
        const float4* src = (const float4*)(g_q + (size_t)(b * L_SZ + i0) * DM);
        float4* dst = (float4*)qs;
        for (int e = tid; e < TI * DM / 4; e += 256) dst[e] = src[e];
    }
    __syncthreads();

    int h = tid >> 5, lane = tid & 31;

    for (int jt = 0; jt < 512 / TJ; jt++) {
        int j0 = jh * 512 + jt * TJ;
        // bias tile -> smem (float4, padded rows)
        for (int e4 = tid; e4 < TI * TJ * 8; e4 += 256) {
            int ti = e4 >> 8; int tj = (e4 >> 3) & 31; int d4 = e4 & 7;
            float4 bv = *(const float4*)(bias + ((size_t)(b * L_SZ + i0 + ti) * L_SZ + (j0 + tj)) * DK + d4 * 4);
            *(float4*)(bs + (ti * TJ + tj) * BS_PAD + d4 * 4) = bv;
        }
        __syncthreads();

        float kreg[DK];
        {
            const float4* kp = (const float4*)(g_k + (size_t)(b * L_SZ + j0 + lane) * DM + h * DK);
            #pragma unroll
            for (int d4 = 0; d4 < 8; d4++) {
                float4 t = kp[d4];
                kreg[d4 * 4 + 0] = t.x; kreg[d4 * 4 + 1] = t.y;
                kreg[d4 * 4 + 2] = t.z; kreg[d4 * 4 + 3] = t.w;
            }
        }
        #pragma unroll 4
        for (int ti = 0; ti < TI; ti++) {
            const float4* q4 = (const float4*)(qs + ti * DM + h * DK);
            const float4* b4 = (const float4*)(bs + (ti * TJ + lane) * BS_PAD);
            float s1 = 0.f, s2 = 0.f;
            #pragma unroll
            for (int d4 = 0; d4 < 8; d4++) {
                float4 qv = q4[d4]; float4 bv = b4[d4];
                s1 = fmaf(qv.x, kreg[d4 * 4 + 0], s1); s2 = fmaf(qv.x, bv.x, s2);
                s1 = fmaf(qv.y, kreg[d4 * 4 + 1], s1); s2 = fmaf(qv.y, bv.y, s2);
                s1 = fmaf(qv.z, kreg[d4 * 4 + 2], s1); s2 = fmaf(qv.z, bv.z, s2);
                s1 = fmaf(qv.w, kreg[d4 * 4 + 3], s1); s2 = fmaf(qv.w, bv.w, s2);
            }
            attn[((size_t)((h * B_SZ + b) * L_SZ + (i0 + ti))) * L_SZ + j0 + lane] =
                (s1 + s2) * INV_SQRT_DK;
        }
        __syncthreads();
    }
}

// ---------------------------------------------------------------
// Row softmax in place over last dim (1024). One CTA per row.
// ---------------------------------------------------------------
__global__ void softmax_kernel(float* __restrict__ attn)
{
    size_t base = (size_t)blockIdx.x * L_SZ;
    int tid = threadIdx.x;
    float x0 = attn[base + tid];
    float x1 = attn[base + tid + 256];
    float x2 = attn[base + tid + 512];
    float x3 = attn[base + tid + 768];

    float m = fmaxf(fmaxf(x0, x1), fmaxf(x2, x3));
    #pragma unroll
    for (int o = 16; o; o >>= 1) m = fmaxf(m, __shfl_xor_sync(0xffffffffu, m, o));

    __shared__ float red[8];
    __shared__ float bval;
    if ((tid & 31) == 0) red[tid >> 5] = m;
    __syncthreads();
    if (tid == 0) {
        float mm = red[0];
        #pragma unroll
        for (int i = 1; i < 8; i++) mm = fmaxf(mm, red[i]);
        bval = mm;
    }
    __syncthreads();
    float M = bval;

    float e0 = __expf(x0 - M), e1 = __expf(x1 - M);
    float e2 = __expf(x2 - M), e3 = __expf(x3 - M);
    float s = e0 + e1 + e2 + e3;
    #pragma unroll
    for (int o = 16; o; o >>= 1) s += __shfl_xor_sync(0xffffffffu, s, o);
    __syncthreads();
    if ((tid & 31) == 0) red[tid >> 5] = s;
    __syncthreads();
    if (tid == 0) {
        float ss = 0.f;
        #pragma unroll
        for (int i = 0; i < 8; i++) ss += red[i];
        bval = 1.0f / ss;
    }
    __syncthreads();
    float inv = bval;
    attn[base + tid]       = e0 * inv;
    attn[base + tid + 256] = e1 * inv;
    attn[base + tid + 512] = e2 * inv;
    attn[base + tid + 768] = e3 * inv;
}

// ---------------------------------------------------------------
// emb[b,i,h,d] = sum_j attn[h,b,i,j] * (v[b,j,h,d])  +  attn * bias[b,i,j,d]
// Grid NROWS/TI. Thread -> (ti = t>>4, h = (t&15)>>1, d-half = t&1).
// ---------------------------------------------------------------
__global__ void emb_kernel(const float* __restrict__ bias,
                           const float* __restrict__ attn)
{
    extern __shared__ float sm[];
    float* vs = sm;                         // TJ*H*VS_PAD = 8448 floats
    float* bs = sm + TJ * H_SZ * VS_PAD;    // TI*TJ*BS_PAD = 18432 floats

    int tid = threadIdx.x;
    int r0  = blockIdx.x * TI;
    int b   = r0 >> 10;
    int i0  = r0 & (L_SZ - 1);

    int ti  = tid >> 4;
    int rem = tid & 15;
    int hh  = rem >> 1;
    int d0  = (rem & 1) * 16;

    float acc[16];
    #pragma unroll
    for (int d = 0; d < 16; d++) acc[d] = 0.f;

    for (int jt = 0; jt < L_SZ / TJ; jt++) {
        int j0 = jt * TJ;
        // v tile -> smem [j][h][33]
        for (int e = tid; e < TJ * DM; e += 256) {
            int j = e >> 8; int c = e & 255;
            vs[(j * H_SZ + (c >> 5)) * VS_PAD + (c & 31)] =
                g_v[(size_t)(b * L_SZ + j0 + j) * DM + c];
        }
        // bias tile -> smem (float4, padded)
        for (int e4 = tid; e4 < TI * TJ * 8; e4 += 256) {
            int tii = e4 >> 8; int tj = (e4 >> 3) & 31; int d4 = e4 & 7;
            float4 bv = *(const float4*)(bias + ((size_t)(b * L_SZ + i0 + tii) * L_SZ + (j0 + tj)) * DK + d4 * 4);
            *(float4*)(bs + (tii * TJ + tj) * BS_PAD + d4 * 4) = bv;
        }
        __syncthreads();

        float areg[TJ];
        {
            const float4* ap = (const float4*)(attn +
                ((size_t)((hh * B_SZ + b) * L_SZ + (i0 + ti))) * L_SZ + j0);
            #pragma unroll
            for (int q4 = 0; q4 < 8; q4++) {
                float4 t = ap[q4];
                areg[q4 * 4 + 0] = t.x; areg[q4 * 4 + 1] = t.y;
                areg[q4 * 4 + 2] = t.z; areg[q4 * 4 + 3] = t.w;
            }
        }
        #pragma unroll 4
        for (int j = 0; j < TJ; j++) {
            float a = areg[j];
            const float* vrow = vs + (j * H_SZ + hh) * VS_PAD + d0;
            const float* brow = bs + (ti * TJ + j) * BS_PAD + d0;
            #pragma unroll
            for (int dd = 0; dd < 16; dd++) {
                acc[dd] = fmaf(a, vrow[dd], acc[dd]);
                acc[dd] = fmaf(a, brow[dd], acc[dd]);
            }
        }
        __syncthreads();
    }
    float* ep = g_emb + (size_t)(b * L_SZ + i0 + ti) * DM + hh * DK + d0;
    #pragma unroll
    for (int dd = 0; dd < 16; dd++) ep[dd] = acc[dd];
}

// ---------------------------------------------------------------
extern "C" void kernel_launch(void* const* d_in, const int* in_sizes, int n_in,
                              void* d_out, int out_size)
{
    const float* h    = (const float*)d_in[0];
    const float* bias = (const float*)d_in[1];
    const float* w_qs = (const float*)d_in[2];
    const float* w_ks = (const float*)d_in[3];
    const float* w_vs = (const float*)d_in[4];
    const float* ln_g = (const float*)d_in[5];
    const float* ln_b = (const float*)d_in[6];
    const float* fc_w = (const float*)d_in[7];
    const float* fc_b = (const float*)d_in[8];

    float* out  = (float*)d_out;                       // (B, L, 256)
    float* attn = out + (size_t)B_SZ * L_SZ * DM;      // (H, B, L, L)

    void *p_hn, *p_q, *p_k, *p_v, *p_emb;
    cudaGetSymbolAddress(&p_hn,  g_hn);
    cudaGetSymbolAddress(&p_q,   g_q);
    cudaGetSymbolAddress(&p_k,   g_k);
    cudaGetSymbolAddress(&p_v,   g_v);
    cudaGetSymbolAddress(&p_emb, g_emb);

    const size_t SMEM_SC  = (size_t)(TI * DM + TI * TJ * BS_PAD) * sizeof(float);      // 90112
    const size_t SMEM_EMB = (size_t)(TJ * H_SZ * VS_PAD + TI * TJ * BS_PAD) * sizeof(float); // 107520
    cudaFuncSetAttribute(scores_kernel, cudaFuncAttributeMaxDynamicSharedMemorySize, (int)SMEM_SC);
    cudaFuncSetAttribute(emb_kernel,    cudaFuncAttributeMaxDynamicSharedMemorySize, (int)SMEM_EMB);

    // 1. LayerNorm
    ln_kernel<<<NROWS, 256>>>(h, ln_g, ln_b);

    // 2. Q/K/V projections
    dim3 ggrid(DM / 64, NROWS / 64);
    gemm_abt_kernel<<<ggrid, 256>>>((const float*)p_hn, w_qs, nullptr, nullptr, (float*)p_q, NROWS, DM, DM);
    gemm_abt_kernel<<<ggrid, 256>>>((const float*)p_hn, w_ks, nullptr, nullptr, (float*)p_k, NROWS, DM, DM);
    gemm_abt_kernel<<<ggrid, 256>>>((const float*)p_hn, w_vs, nullptr, nullptr, (float*)p_v, NROWS, DM, DM);

    // 3. Raw scores -> attn region
    scores_kernel<<<dim3(2, NROWS / TI), 256, SMEM_SC>>>(bias, attn);

    // 4. Softmax rows in place
    softmax_kernel<<<H_SZ * B_SZ * L_SZ, 256>>>(attn);

    // 5. emb = attn@v + attn@bias
    emb_kernel<<<NROWS / TI, 256, SMEM_EMB>>>(bias, attn);

    // 6. out = emb @ fc_w^T + fc_b + residual
    gemm_abt_kernel<<<ggrid, 256>>>((const float*)p_emb, fc_w, fc_b, h, out, NROWS, DM, DM);
}